// round 1
// baseline (speedup 1.0000x reference)
#include <cuda_runtime.h>

#define Vn 50000
#define NNZn 1600000
#define Bn 4
#define FINn 128
#define FOUTn 128
#define Kn 5
#define Cn 512  // FIN * B columns per Chebyshev buffer (internal layout: col = b*128 + fi)

// Scratch (device globals: allocation-free rule)
__device__ float g_T[(size_t)Kn * Vn * Cn];   // 5 x [V,512] Chebyshev terms, 512MB
__device__ int   g_cnt[Vn];
__device__ int   g_rowptr[Vn + 1];
__device__ int   g_fill[Vn];
__device__ int   g_ccol[NNZn];
__device__ float g_cval[NNZn];

// ---------------- pack: inputs[B,V,FIN] -> T0[v, b*128+f] ----------------
__global__ void pack_x0_kernel(const float* __restrict__ inp) {
    size_t i = (size_t)blockIdx.x * blockDim.x + threadIdx.x;  // float4 index
    if (i >= (size_t)Vn * 128) return;
    int v    = (int)(i >> 7);
    int col4 = (int)(i & 127);      // col4 = b*32 + f4
    int b    = col4 >> 5;
    int f4   = col4 & 31;
    float4 val = ((const float4*)inp)[((size_t)b * Vn + v) * 32 + f4];
    ((float4*)g_T)[i] = val;
}

// ---------------- CSR build ----------------
__global__ void zero_cnt_kernel() {
    int i = blockIdx.x * blockDim.x + threadIdx.x;
    if (i < Vn) g_cnt[i] = 0;
}

__global__ void hist_kernel(const int* __restrict__ rows) {
    int e = blockIdx.x * blockDim.x + threadIdx.x;
    if (e < NNZn) atomicAdd(&g_cnt[rows[e]], 1);
}

__global__ void scan_kernel() {
    __shared__ int tmp[1024];
    __shared__ int carry;
    if (threadIdx.x == 0) carry = 0;
    __syncthreads();
    for (int base = 0; base < Vn; base += 1024) {
        int i = base + threadIdx.x;
        int x = (i < Vn) ? g_cnt[i] : 0;
        tmp[threadIdx.x] = x;
        __syncthreads();
        #pragma unroll
        for (int off = 1; off < 1024; off <<= 1) {
            int t = 0;
            if (threadIdx.x >= (unsigned)off) t = tmp[threadIdx.x - off];
            __syncthreads();
            tmp[threadIdx.x] += t;
            __syncthreads();
        }
        int excl = tmp[threadIdx.x] - x;
        if (i < Vn) {
            int p = carry + excl;
            g_rowptr[i] = p;
            g_fill[i]   = p;
        }
        __syncthreads();
        if (threadIdx.x == 1023) carry += tmp[1023];
        __syncthreads();
    }
    if (threadIdx.x == 0) g_rowptr[Vn] = carry;
}

__global__ void scatter_kernel(const int* __restrict__ rows,
                               const int* __restrict__ cols,
                               const float* __restrict__ vals) {
    int e = blockIdx.x * blockDim.x + threadIdx.x;
    if (e < NNZn) {
        int r = rows[e];
        int p = atomicAdd(&g_fill[r], 1);
        g_ccol[p] = cols[e];
        g_cval[p] = vals[e];
    }
}

// ---------------- SpMM: dst = alpha * (L @ src) [- other] ----------------
// One block (128 threads) per row; each thread owns one float4 of the 512-wide row.
__global__ __launch_bounds__(128) void spmm_kernel(int src_idx, int other_idx,
                                                   int dst_idx, float alpha,
                                                   int has_other) {
    const float4* src4 = (const float4*)(g_T + (size_t)src_idx * Vn * Cn);
    float4* dst4       = (float4*)(g_T + (size_t)dst_idx * Vn * Cn);

    int r = blockIdx.x;
    int t = threadIdx.x;
    int s = g_rowptr[r];
    int e = g_rowptr[r + 1];

    float4 acc = make_float4(0.f, 0.f, 0.f, 0.f);
    int i = s;
    for (; i + 4 <= e; i += 4) {
        int   c0 = __ldg(&g_ccol[i + 0]), c1 = __ldg(&g_ccol[i + 1]);
        int   c2 = __ldg(&g_ccol[i + 2]), c3 = __ldg(&g_ccol[i + 3]);
        float w0 = __ldg(&g_cval[i + 0]), w1 = __ldg(&g_cval[i + 1]);
        float w2 = __ldg(&g_cval[i + 2]), w3 = __ldg(&g_cval[i + 3]);
        float4 x0 = src4[(size_t)c0 * 128 + t];
        float4 x1 = src4[(size_t)c1 * 128 + t];
        float4 x2 = src4[(size_t)c2 * 128 + t];
        float4 x3 = src4[(size_t)c3 * 128 + t];
        acc.x += w0 * x0.x + w1 * x1.x + w2 * x2.x + w3 * x3.x;
        acc.y += w0 * x0.y + w1 * x1.y + w2 * x2.y + w3 * x3.y;
        acc.z += w0 * x0.z + w1 * x1.z + w2 * x2.z + w3 * x3.z;
        acc.w += w0 * x0.w + w1 * x1.w + w2 * x2.w + w3 * x3.w;
    }
    for (; i < e; i++) {
        int   c = __ldg(&g_ccol[i]);
        float w = __ldg(&g_cval[i]);
        float4 xv = src4[(size_t)c * 128 + t];
        acc.x += w * xv.x; acc.y += w * xv.y; acc.z += w * xv.z; acc.w += w * xv.w;
    }

    acc.x *= alpha; acc.y *= alpha; acc.z *= alpha; acc.w *= alpha;
    if (has_other) {
        const float4* oth4 = (const float4*)(g_T + (size_t)other_idx * Vn * Cn);
        float4 o = oth4[(size_t)r * 128 + t];
        acc.x -= o.x; acc.y -= o.y; acc.z -= o.z; acc.w -= o.w;
    }
    dst4[(size_t)r * 128 + t] = acc;
}

// ---------------- GEMM ----------------
// out[b,v,fo] = bias[fo] + sum_{fi,k} T_k[v, b*128+fi] * Wflat[fi*5+k][fo]
// (replicates reference's (fi,k)-column x (k,fi)-row pairing exactly)
// Tile: BM=64 (v), BN=128 (all fo), BK=40 (8 fi x 5 k). 256 threads, TM=8, TN=4.
#define BM 64
#define BN 128
#define BK 40

__global__ __launch_bounds__(256) void gemm_kernel(const float* __restrict__ wt,
                                                   const float* __restrict__ bias,
                                                   float* __restrict__ out) {
    __shared__ float As[BK][BM];
    __shared__ float Bs[BK][BN];

    int b  = blockIdx.y;
    int v0 = blockIdx.x * BM;
    int t  = threadIdx.x;
    int tx = t & 31;        // N position: cols tx*4..tx*4+3
    int ty = t >> 5;        // M position: rows ty*8..ty*8+7

    float acc[8][4];
    #pragma unroll
    for (int m = 0; m < 8; m++)
        #pragma unroll
        for (int n = 0; n < 4; n++) acc[m][n] = 0.f;

    int boff = b * 128;

    for (int tile = 0; tile < 16; tile++) {
        int fi0 = tile * 8;       // 8 fi values per tile
        int j0  = fi0 * 5;        // 40 logical K-columns per tile

        // Load A: per (m, k): two float4 (8 consecutive fi) from buffer k.
        // idx in [0,640): m = idx/10, k = (idx%10)>>1, f2 = idx&1
        for (int idx = t; idx < 640; idx += 256) {
            int m   = idx / 10;
            int rem = idx % 10;
            int k   = rem >> 1;
            int f2  = rem & 1;
            int v   = v0 + m;
            float4 av = make_float4(0.f, 0.f, 0.f, 0.f);
            if (v < Vn) {
                const float* src = g_T + (size_t)k * Vn * Cn +
                                   (size_t)v * Cn + boff + fi0 + f2 * 4;
                av = *(const float4*)src;
            }
            int base = f2 * 4;
            As[(base + 0) * 5 + k][m] = av.x;
            As[(base + 1) * 5 + k][m] = av.y;
            As[(base + 2) * 5 + k][m] = av.z;
            As[(base + 3) * 5 + k][m] = av.w;
        }

        // Load B: 40 x 128 floats = 1280 float4, 5 per thread, coalesced.
        for (int idx = t; idx < 1280; idx += 256) {
            int j  = idx >> 5;
            int n4 = idx & 31;
            *(float4*)&Bs[j][n4 * 4] =
                ((const float4*)wt)[(size_t)(j0 + j) * 32 + n4];
        }
        __syncthreads();

        #pragma unroll
        for (int j = 0; j < BK; j++) {
            float4 a0 = *(const float4*)&As[j][ty * 8];
            float4 a1 = *(const float4*)&As[j][ty * 8 + 4];
            float4 bv = *(const float4*)&Bs[j][tx * 4];
            float a[8] = {a0.x, a0.y, a0.z, a0.w, a1.x, a1.y, a1.z, a1.w};
            #pragma unroll
            for (int m = 0; m < 8; m++) {
                acc[m][0] += a[m] * bv.x;
                acc[m][1] += a[m] * bv.y;
                acc[m][2] += a[m] * bv.z;
                acc[m][3] += a[m] * bv.w;
            }
        }
        __syncthreads();
    }

    float4 bb = *(const float4*)&bias[tx * 4];
    #pragma unroll
    for (int m = 0; m < 8; m++) {
        int v = v0 + ty * 8 + m;
        if (v < Vn) {
            float4 o = make_float4(acc[m][0] + bb.x, acc[m][1] + bb.y,
                                   acc[m][2] + bb.z, acc[m][3] + bb.w);
            ((float4*)out)[((size_t)b * Vn + v) * 32 + tx] = o;
        }
    }
}

// ---------------- launch ----------------
extern "C" void kernel_launch(void* const* d_in, const int* in_sizes, int n_in,
                              void* d_out, int out_size) {
    const int*   rows = (const int*)d_in[0];
    const int*   cols = (const int*)d_in[1];
    const float* vals = (const float*)d_in[2];
    const float* inp  = (const float*)d_in[3];
    const float* wt   = (const float*)d_in[4];
    const float* bias = (const float*)d_in[5];
    float*       out  = (float*)d_out;

    // T0 = packed inputs
    pack_x0_kernel<<<(Vn * 128 + 255) / 256, 256>>>(inp);

    // CSR build (per-call; deterministic up to nnz order within a row,
    // which only perturbs fp32 rounding far below the 1e-3 threshold)
    zero_cnt_kernel<<<(Vn + 255) / 256, 256>>>();
    hist_kernel<<<(NNZn + 255) / 256, 256>>>(rows);
    scan_kernel<<<1, 1024>>>();
    scatter_kernel<<<(NNZn + 255) / 256, 256>>>(rows, cols, vals);

    // Chebyshev recursion
    spmm_kernel<<<Vn, 128>>>(0, 0, 1, 1.0f, 0);  // T1 = L@T0
    spmm_kernel<<<Vn, 128>>>(1, 0, 2, 2.0f, 1);  // T2 = 2 L@T1 - T0
    spmm_kernel<<<Vn, 128>>>(2, 1, 3, 2.0f, 1);  // T3 = 2 L@T2 - T1
    spmm_kernel<<<Vn, 128>>>(3, 2, 4, 2.0f, 1);  // T4 = 2 L@T3 - T2

    // Combine + bias
    dim3 ggrid((Vn + BM - 1) / BM, Bn);
    gemm_kernel<<<ggrid, 256>>>(wt, bias, out);
}

// round 3
// speedup vs baseline: 1.3588x; 1.3588x over previous
#include <cuda_runtime.h>
#include <cuda_bf16.h>
#include <cstdint>

#define Vn 50000
#define NNZn 1600000
#define Bn 4
#define Cn 512            // FIN*B columns per Chebyshev buffer (col = b*128 + fi)
#define Mtot 200000       // B*V GEMM rows
#define KD 640            // FIN*K logical GEMM K-dim (j' = fi*5 + k)

// ---------------- device scratch (allocation-free rule) ----------------
__device__ float g_T[(size_t)5 * Vn * Cn];      // 5 x [V,512] fp32 Chebyshev terms
__device__ int   g_cnt[Vn];
__device__ int   g_rowptr[Vn + 1];
__device__ int   g_fill[Vn];
__device__ int   g_ccol[NNZn];
__device__ float g_cval[NNZn];
__device__ int   g_bsum[64];
__device__ int   g_boff[64];
__device__ __nv_bfloat16 g_Whi[128 * KD];       // W^T: [n][j'] bf16 hi
__device__ __nv_bfloat16 g_Wlo[128 * KD];       // W^T: [n][j'] bf16 lo

__device__ __forceinline__ uint32_t smem_u32(const void* p) {
    uint32_t a;
    asm("{ .reg .u64 t; cvta.to.shared.u64 t, %1; cvt.u32.u64 %0, t; }"
        : "=r"(a) : "l"(p));
    return a;
}

__device__ __forceinline__ void ldm_x4(uint32_t* r, uint32_t addr) {
    asm volatile("ldmatrix.sync.aligned.m8n8.x4.shared.b16 {%0,%1,%2,%3}, [%4];"
                 : "=r"(r[0]), "=r"(r[1]), "=r"(r[2]), "=r"(r[3]) : "r"(addr));
}

__device__ __forceinline__ void mma_bf16(float* c, const uint32_t* a,
                                         uint32_t b0, uint32_t b1) {
    asm volatile(
        "mma.sync.aligned.m16n8k16.row.col.f32.bf16.bf16.f32 "
        "{%0,%1,%2,%3}, {%4,%5,%6,%7}, {%8,%9}, {%0,%1,%2,%3};"
        : "+f"(c[0]), "+f"(c[1]), "+f"(c[2]), "+f"(c[3])
        : "r"(a[0]), "r"(a[1]), "r"(a[2]), "r"(a[3]), "r"(b0), "r"(b1));
}

// ---------------- pack: inputs[B,V,FIN] -> T0[v, b*128+f] ----------------
__global__ void pack_x0_kernel(const float* __restrict__ inp) {
    size_t i = (size_t)blockIdx.x * blockDim.x + threadIdx.x;
    if (i >= (size_t)Vn * 128) return;
    int v    = (int)(i >> 7);
    int col4 = (int)(i & 127);
    int b    = col4 >> 5;
    int f4   = col4 & 31;
    ((float4*)g_T)[i] = ((const float4*)inp)[((size_t)b * Vn + v) * 32 + f4];
}

// ---------------- W pack: wt[j'][n] fp32 -> W^T[n][j'] bf16 hi/lo ----------------
__global__ void wpack_kernel(const float* __restrict__ wt) {
    int idx = blockIdx.x * blockDim.x + threadIdx.x;
    if (idx >= 128 * KD) return;
    int j = idx >> 7, n = idx & 127;
    float a = wt[idx];
    __nv_bfloat16 h = __float2bfloat16(a);
    g_Whi[n * KD + j] = h;
    g_Wlo[n * KD + j] = __float2bfloat16(a - __bfloat162float(h));
}

// ---------------- CSR build ----------------
__global__ void zero_cnt_kernel() {
    int i = blockIdx.x * blockDim.x + threadIdx.x;
    if (i < Vn) g_cnt[i] = 0;
}
__global__ void hist_kernel(const int* __restrict__ rows) {
    int e = blockIdx.x * blockDim.x + threadIdx.x;
    if (e < NNZn) atomicAdd(&g_cnt[rows[e]], 1);
}
__global__ __launch_bounds__(1024) void scan1_kernel() {
    __shared__ int tmp[1024];
    int i = blockIdx.x * 1024 + threadIdx.x;
    int x = (i < Vn) ? g_cnt[i] : 0;
    tmp[threadIdx.x] = x;
    __syncthreads();
    #pragma unroll
    for (int off = 1; off < 1024; off <<= 1) {
        int t = 0;
        if (threadIdx.x >= (unsigned)off) t = tmp[threadIdx.x - off];
        __syncthreads();
        tmp[threadIdx.x] += t;
        __syncthreads();
    }
    if (i < Vn) g_rowptr[i] = tmp[threadIdx.x] - x;   // block-local exclusive
    if (threadIdx.x == 1023) g_bsum[blockIdx.x] = tmp[1023];
}
__global__ void scan2_kernel(int nblk) {
    if (threadIdx.x == 0) {
        int acc = 0;
        for (int j = 0; j < nblk; j++) { g_boff[j] = acc; acc += g_bsum[j]; }
        g_rowptr[Vn] = acc;
    }
}
__global__ __launch_bounds__(1024) void scan3_kernel() {
    int i = blockIdx.x * 1024 + threadIdx.x;
    if (i < Vn) {
        int p = g_rowptr[i] + g_boff[blockIdx.x];
        g_rowptr[i] = p;
        g_fill[i]   = p;
    }
}
__global__ void scatter_kernel(const int* __restrict__ rows,
                               const int* __restrict__ cols,
                               const float* __restrict__ vals) {
    int e = blockIdx.x * blockDim.x + threadIdx.x;
    if (e < NNZn) {
        int r = rows[e];
        int p = atomicAdd(&g_fill[r], 1);
        g_ccol[p] = cols[e];
        g_cval[p] = vals[e];
    }
}

// ---------------- SpMM: dst = alpha * (L @ src) [- other] ----------------
__global__ __launch_bounds__(128) void spmm_kernel(int src_idx, int other_idx,
                                                   int dst_idx, float alpha,
                                                   int has_other) {
    const float4* src4 = (const float4*)(g_T + (size_t)src_idx * Vn * Cn);
    float4* dst4       = (float4*)(g_T + (size_t)dst_idx * Vn * Cn);

    int r = blockIdx.x;
    int t = threadIdx.x;
    int s = g_rowptr[r];
    int e = g_rowptr[r + 1];

    float4 acc = make_float4(0.f, 0.f, 0.f, 0.f);
    int i = s;
    for (; i + 8 <= e; i += 8) {
        int   c[8];
        float w[8];
        #pragma unroll
        for (int u = 0; u < 8; u++) {
            c[u] = __ldg(&g_ccol[i + u]);
            w[u] = __ldg(&g_cval[i + u]);
        }
        float4 x[8];
        #pragma unroll
        for (int u = 0; u < 8; u++) x[u] = src4[(size_t)c[u] * 128 + t];
        #pragma unroll
        for (int u = 0; u < 8; u++) {
            acc.x += w[u] * x[u].x; acc.y += w[u] * x[u].y;
            acc.z += w[u] * x[u].z; acc.w += w[u] * x[u].w;
        }
    }
    for (; i < e; i++) {
        int   c = __ldg(&g_ccol[i]);
        float w = __ldg(&g_cval[i]);
        float4 xv = src4[(size_t)c * 128 + t];
        acc.x += w * xv.x; acc.y += w * xv.y; acc.z += w * xv.z; acc.w += w * xv.w;
    }

    acc.x *= alpha; acc.y *= alpha; acc.z *= alpha; acc.w *= alpha;
    if (has_other) {
        const float4* oth4 = (const float4*)(g_T + (size_t)other_idx * Vn * Cn);
        float4 o = oth4[(size_t)r * 128 + t];
        acc.x -= o.x; acc.y -= o.y; acc.z -= o.z; acc.w -= o.w;
    }
    dst4[(size_t)r * 128 + t] = acc;
}

// ---------------- mma.sync GEMM with fused A conversion/scramble ----------------
// out[m][n] = bias[n] + sum_j' A[m][j'] W[j'][n], A[m][fi*5+k] = T_k[v][b*128+fi].
// Tile: BM=128 (block), BN=128, BK=80 (16 fi x 5 k). 8 warps, warp tile 32x64.
// bf16 3-term split (hi*hi + hi*lo + lo*hi), fp32 accum.
#define SROW 88               // smem row stride in elements (176B): ldmatrix conflict-free
#define SA_HI 0
#define SA_LO (128 * 176)
#define SW_HI (2 * 128 * 176)
#define SW_LO (3 * 128 * 176)
#define GEMM_SMEM (4 * 128 * 176)   // 90112 B

__global__ __launch_bounds__(256, 1) void gemm_mma_kernel(const float* __restrict__ bias,
                                                          float* __restrict__ out) {
    extern __shared__ __align__(16) char smem[];
    uint32_t sb = smem_u32(smem);
    int tid = threadIdx.x;
    int l   = tid & 31;
    int wid = tid >> 5;
    int wm  = wid >> 1;          // 0..3: M position
    int wn  = wid & 1;           // 0..1: N position
    int m0  = blockIdx.x * 128;

    float acc[2][8][4];
    #pragma unroll
    for (int mt = 0; mt < 2; mt++)
        #pragma unroll
        for (int nt = 0; nt < 8; nt++)
            #pragma unroll
            for (int q = 0; q < 4; q++) acc[mt][nt][q] = 0.f;

    for (int c = 0; c < 8; c++) {
        int fi0 = c * 16;
        int j0  = c * 80;
        __syncthreads();   // previous chunk fully consumed

        // --- A loader: read fp32 g_T, convert to bf16 hi/lo, scramble j'=fi*5+k ---
        #pragma unroll
        for (int t2 = 0; t2 < 2; t2++) {
            int idx = t2 * 256 + tid;       // 0..511
            int row = idx >> 2;             // 0..127
            int g   = idx & 3;              // fi group (4 fi each)
            int m   = m0 + row;
            union { __nv_bfloat16 h[20]; uint2 q[5]; } Uh, Ul;
            if (m < Mtot) {
                int b = m / Vn;
                int v = m - b * Vn;
                const float* base = g_T + (size_t)v * Cn + b * 128 + fi0 + g * 4;
                #pragma unroll
                for (int k = 0; k < 5; k++) {
                    float4 x = *(const float4*)(base + (size_t)k * Vn * Cn);
                    float cc[4] = {x.x, x.y, x.z, x.w};
                    #pragma unroll
                    for (int u = 0; u < 4; u++) {
                        __nv_bfloat16 h = __float2bfloat16(cc[u]);
                        Uh.h[u * 5 + k] = h;
                        Ul.h[u * 5 + k] = __float2bfloat16(cc[u] - __bfloat162float(h));
                    }
                }
            } else {
                #pragma unroll
                for (int p = 0; p < 5; p++) {
                    Uh.q[p] = make_uint2(0u, 0u);
                    Ul.q[p] = make_uint2(0u, 0u);
                }
            }
            char* dh = smem + SA_HI + row * 176 + g * 40;
            char* dl = smem + SA_LO + row * 176 + g * 40;
            #pragma unroll
            for (int p = 0; p < 5; p++) {
                *(uint2*)(dh + p * 8) = Uh.q[p];
                *(uint2*)(dl + p * 8) = Ul.q[p];
            }
        }

        // --- W loader: already scrambled (flat row index IS j') ---
        #pragma unroll
        for (int t5 = 0; t5 < 5; t5++) {
            int idx = t5 * 256 + tid;       // 0..1279
            int n   = idx / 10;
            int u8  = idx % 10;             // 8-element group within 80
            float4 h4 = *(const float4*)(g_Whi + (size_t)n * KD + j0 + u8 * 8);
            float4 l4 = *(const float4*)(g_Wlo + (size_t)n * KD + j0 + u8 * 8);
            *(float4*)(smem + SW_HI + n * 176 + u8 * 16) = h4;
            *(float4*)(smem + SW_LO + n * 176 + u8 * 16) = l4;
        }
        __syncthreads();

        // --- compute: 5 k16 steps ---
        #pragma unroll
        for (int ks = 0; ks < 5; ks++) {
            int k0 = ks * 16;
            uint32_t ah[2][4], al[2][4], bh[4][4], bl[4][4];
            #pragma unroll
            for (int mt = 0; mt < 2; mt++) {
                uint32_t off = (uint32_t)((wm * 32 + mt * 16 + (l & 15)) * 176 +
                                          (k0 + (l >> 4) * 8) * 2);
                ldm_x4(ah[mt], sb + SA_HI + off);
                ldm_x4(al[mt], sb + SA_LO + off);
            }
            #pragma unroll
            for (int pr = 0; pr < 4; pr++) {
                uint32_t off = (uint32_t)((wn * 64 + pr * 16 + (l & 7) + ((l >> 4) & 1) * 8) * 176 +
                                          (k0 + ((l >> 3) & 1) * 8) * 2);
                ldm_x4(bh[pr], sb + SW_HI + off);
                ldm_x4(bl[pr], sb + SW_LO + off);
            }
            #pragma unroll
            for (int mt = 0; mt < 2; mt++) {
                #pragma unroll
                for (int nt = 0; nt < 8; nt++) {
                    int pr = nt >> 1, hf = nt & 1;
                    mma_bf16(acc[mt][nt], ah[mt], bh[pr][hf * 2], bh[pr][hf * 2 + 1]);
                    mma_bf16(acc[mt][nt], ah[mt], bl[pr][hf * 2], bl[pr][hf * 2 + 1]);
                    mma_bf16(acc[mt][nt], al[mt], bh[pr][hf * 2], bh[pr][hf * 2 + 1]);
                }
            }
        }
    }

    // --- epilogue: add bias, store fp32 ---
    #pragma unroll
    for (int mt = 0; mt < 2; mt++) {
        int mrow = m0 + wm * 32 + mt * 16 + (l >> 2);
        #pragma unroll
        for (int nt = 0; nt < 8; nt++) {
            int n = wn * 64 + nt * 8 + (l & 3) * 2;
            float2 bb = *(const float2*)(bias + n);
            if (mrow < Mtot) {
                float2 o0 = make_float2(acc[mt][nt][0] + bb.x, acc[mt][nt][1] + bb.y);
                *(float2*)(out + (size_t)mrow * 128 + n) = o0;
            }
            if (mrow + 8 < Mtot) {
                float2 o1 = make_float2(acc[mt][nt][2] + bb.x, acc[mt][nt][3] + bb.y);
                *(float2*)(out + (size_t)(mrow + 8) * 128 + n) = o1;
            }
        }
    }
}

// ---------------- launch ----------------
extern "C" void kernel_launch(void* const* d_in, const int* in_sizes, int n_in,
                              void* d_out, int out_size) {
    const int*   rows = (const int*)d_in[0];
    const int*   cols = (const int*)d_in[1];
    const float* vals = (const float*)d_in[2];
    const float* inp  = (const float*)d_in[3];
    const float* wt   = (const float*)d_in[4];
    const float* bias = (const float*)d_in[5];
    float*       out  = (float*)d_out;

    cudaFuncSetAttribute(gemm_mma_kernel,
                         cudaFuncAttributeMaxDynamicSharedMemorySize, GEMM_SMEM);

    pack_x0_kernel<<<(Vn * 128 + 255) / 256, 256>>>(inp);
    wpack_kernel<<<(128 * KD + 255) / 256, 256>>>(wt);

    // CSR build
    const int NSCAN = (Vn + 1023) / 1024;   // 49
    zero_cnt_kernel<<<(Vn + 255) / 256, 256>>>();
    hist_kernel<<<(NNZn + 255) / 256, 256>>>(rows);
    scan1_kernel<<<NSCAN, 1024>>>();
    scan2_kernel<<<1, 32>>>(NSCAN);
    scan3_kernel<<<NSCAN, 1024>>>();
    scatter_kernel<<<(NNZn + 255) / 256, 256>>>(rows, cols, vals);

    // Chebyshev recursion
    spmm_kernel<<<Vn, 128>>>(0, 0, 1, 1.0f, 0);  // T1 = L@T0
    spmm_kernel<<<Vn, 128>>>(1, 0, 2, 2.0f, 1);  // T2 = 2 L@T1 - T0
    spmm_kernel<<<Vn, 128>>>(2, 1, 3, 2.0f, 1);  // T3 = 2 L@T2 - T1
    spmm_kernel<<<Vn, 128>>>(3, 2, 4, 2.0f, 1);  // T4 = 2 L@T3 - T2

    // Fused convert+scramble tensor-core GEMM
    gemm_mma_kernel<<<(Mtot + 127) / 128, 256, GEMM_SMEM>>>(bias, out);
}